// round 14
// baseline (speedup 1.0000x reference)
#include <cuda_runtime.h>
#include <cuda_fp16.h>
#include <math.h>

// Problem constants
#define NB 64
#define NA 256
#define NROWS (NB*NA)          // 16384 (b,i) rows
#define AE 20                  // atomemb dim
#define DF 25                  // gaussian features
#define VW_COLS 45             // AE + DF
#define NZ 256                 // z values are in [0, 256)

// Nearest-neighbor fp16 exp-table: 1537 rows over [0,5], split into three
// arrays so each gather instruction sees the max number of bank residues:
//   A: uint4 per row (outputs 0-7),  B: uint4 per row (outputs 8-15),
//   C: uint2 per row (outputs 16-19)
#define TBL 1536
#define TROWS (TBL+1)

#define CTANH 2.885390081777926814f   // 2/ln2
#define QK    0.8521437890f           // e^{-0.16}

// Device scratch (no allocations allowed)
__device__ uint4   d_tA[TROWS];
__device__ uint4   d_tB[TROWS];
__device__ uint2   d_tC[TROWS];
__device__ float4  d_ebz[NZ*5];            // exp(2*base_o) per z value (20KB)
__device__ float   d_weff[AE];
__device__ float   d_beff;

__device__ __forceinline__ float fast_tanh(float x) {
    float e;
    asm("ex2.approx.f32 %0, %1;" : "=f"(e) : "f"(x * CTANH));
    float r;
    asm("rcp.approx.f32 %0, %1;" : "=f"(r) : "f"(e + 1.0f));
    return fmaf(-2.0f, r, 1.0f);
}
__device__ __forceinline__ float rcpf(float x) {
    float r; asm("rcp.approx.f32 %0, %1;" : "=f"(r) : "f"(x)); return r;
}

// ---------- prep kernel: table + per-z eb + weff + zero out ----------
#define TBLOCKS ((TROWS*AE + 255)/256)   // table blocks (121)
#define ZBL     ((NZ*AE + 255)/256)      // per-z eb blocks (20)

__global__ void k_prep(const float* __restrict__ emb,
                       const float* __restrict__ Vw, const float* __restrict__ Vb,
                       const float* __restrict__ W1, const float* __restrict__ b1,
                       const float* __restrict__ W2, const float* __restrict__ b2,
                       float* __restrict__ out) {
    int blk = blockIdx.x;
    if (blk < TBLOCKS) {
        int idx = blk * 256 + threadIdx.x;
        if (idx >= TROWS*AE) return;
        int t = idx / AE;
        int o = idx - t*AE;
        float d = (float)t * (5.0f / (float)TBL);
        // rbf recurrence: rbf_0 = e^{-2d^2}; rbf_{k+1} = rbf_k * s_k;
        //                 s_0 = e^{0.8d - 0.08}; s_{k+1} = s_k * Q
        float rbf = __expf(-2.0f * d * d);
        float s   = __expf(0.8f * d - 0.08f);
        float g = 0.f;
        const float* vwr = Vw + o*VW_COLS + AE;
        #pragma unroll
        for (int k = 0; k < DF; k++) {
            g   = fmaf(__ldg(vwr + k), rbf, g);
            rbf = rbf * s;
            s   = s * QK;
        }
        __half h = __float2half(__expf(2.0f * g));
        if (o < 8)       ((__half*)d_tA)[t*8 + o]      = h;
        else if (o < 16) ((__half*)d_tB)[t*8 + (o-8)]  = h;
        else             ((__half*)d_tC)[t*4 + (o-16)] = h;
    } else if (blk < TBLOCKS + ZBL) {
        int idx = (blk - TBLOCKS) * 256 + threadIdx.x;
        if (idx >= NZ*AE) return;
        int zv = idx / AE;
        int o  = idx - zv*AE;
        float m = (zv != 0) ? 1.f : 0.f;
        float b = Vb[o];
        const float* er  = emb + zv*AE;
        const float* vwr = Vw + o*VW_COLS;
        #pragma unroll
        for (int f = 0; f < AE; f++)
            b = fmaf(m * __ldg(er + f), __ldg(vwr + f), b);
        ((float*)d_ebz)[idx] = __expf(2.0f * b);
    } else {
        int t = threadIdx.x;
        if (t < AE) {
            float s = 0.f;
            #pragma unroll
            for (int m = 0; m < 10; m++) s += W2[m] * W1[m*AE + t];
            d_weff[t] = s;
        }
        if (t == AE) {
            float s = b2[0];
            #pragma unroll
            for (int m = 0; m < 10; m++) s += W2[m] * b1[m];
            d_beff = s;
        }
        if (t >= 128 && t < 128 + NB) out[t - 128] = 0.f;   // zero accumulators
    }
}

// process 4 outputs from two half2 words (batch-4 reciprocal — proven optimum)
__device__ __forceinline__ void group4(unsigned w0, unsigned w1,
                                       const float* eb, float* acc) {
    float2 a = __half22float2(*(const __half2*)&w0);
    float2 b = __half22float2(*(const __half2*)&w1);
    float y0 = fmaf(a.x, eb[0], 1.0f);
    float y1 = fmaf(a.y, eb[1], 1.0f);
    float y2 = fmaf(b.x, eb[2], 1.0f);
    float y3 = fmaf(b.y, eb[3], 1.0f);
    float t01 = y0 * y1, t23 = y2 * y3;
    float r   = rcpf(t01 * t23);
    float r01 = r * t23, r23 = r * t01;
    acc[0] = fmaf(r01, y1, acc[0]);   // += 1/y0
    acc[1] = fmaf(r01, y0, acc[1]);   // += 1/y1
    acc[2] = fmaf(r23, y3, acc[2]);
    acc[3] = fmaf(r23, y2, acc[3]);
}

// smem layout (bytes)
#define SM_A 0
#define SM_B (TROWS*16)
#define SM_C (TROWS*32)
#define SM_TOTAL (TROWS*32 + TROWS*8)   // 61480 B

// ---------- main: one warp per (b,i) row; split-array gathers ----------
__global__ void __launch_bounds__(384, 2)
k_main(const float* __restrict__ dist, const int* __restrict__ z,
       const float* __restrict__ emb, float* __restrict__ out) {
    extern __shared__ char smem[];
    uint4* smA = (uint4*)(smem + SM_A);
    uint4* smB = (uint4*)(smem + SM_B);
    uint2* smC = (uint2*)(smem + SM_C);
    const int tid = threadIdx.x;
    for (int i = tid; i < TROWS; i += blockDim.x) {
        smA[i] = d_tA[i];
        smB[i] = d_tB[i];
        smC[i] = d_tC[i];
    }
    __syncthreads();

    const int lane = tid & 31;
    const int nwarps = gridDim.x * (blockDim.x >> 5);
    int gw = blockIdx.x * (blockDim.x >> 5) + (tid >> 5);

    for (int row = gw; row < NROWS; row += nwarps) {
        const int zi = __ldg(z + row);            // uniform
        // eb: 5 uniform float4 loads from 20KB L1-resident per-z table
        float eb[AE], acc[AE];
        {
            const float4* e4 = d_ebz + zi*5;
            float4 v0 = __ldg(e4+0), v1 = __ldg(e4+1), v2 = __ldg(e4+2),
                   v3 = __ldg(e4+3), v4 = __ldg(e4+4);
            eb[0]=v0.x; eb[1]=v0.y; eb[2]=v0.z; eb[3]=v0.w;
            eb[4]=v1.x; eb[5]=v1.y; eb[6]=v1.z; eb[7]=v1.w;
            eb[8]=v2.x; eb[9]=v2.y; eb[10]=v2.z; eb[11]=v2.w;
            eb[12]=v3.x; eb[13]=v3.y; eb[14]=v3.z; eb[15]=v3.w;
            eb[16]=v4.x; eb[17]=v4.y; eb[18]=v4.z; eb[19]=v4.w;
        }
        #pragma unroll
        for (int o = 0; o < AE; o++) acc[o] = 0.f;

        // lane handles j = lane*8 .. lane*8+7
        const float4* drow4 = (const float4*)(dist + (size_t)row * NA + lane * 8);
        float4 dv0 = __ldg(drow4);
        float4 dv1 = __ldg(drow4 + 1);
        float dv[8] = {dv0.x, dv0.y, dv0.z, dv0.w, dv1.x, dv1.y, dv1.z, dv1.w};

        #pragma unroll
        for (int jt = 0; jt < 8; jt++) {
            int ti = __float2int_rn(dv[jt] * ((float)TBL / 5.0f));
            uint4 qa = smA[ti];
            uint4 qb = smB[ti];
            uint2 qc = smC[ti];
            group4(qa.x, qa.y, eb +  0, acc +  0);
            group4(qa.z, qa.w, eb +  4, acc +  4);
            group4(qb.x, qb.y, eb +  8, acc +  8);
            group4(qb.z, qb.w, eb + 12, acc + 12);
            group4(qc.x, qc.y, eb + 16, acc + 16);
        }

        // ---- exchange-split hierarchical reduction ----
        // level 1 (xor16): lo lanes keep outputs 0..9, hi lanes 10..19.
        // One shuffle moves the half each side is giving away.
        float v[10];
        {
            bool hi = (lane & 16);
            #pragma unroll
            for (int k = 0; k < 10; k++) {
                float s = hi ? acc[k] : acc[k+10];
                float t = __shfl_xor_sync(0xffffffffu, s, 16);
                v[k] = (hi ? acc[k+10] : acc[k]) + t;
            }
        }
        // level 2 (xor8): groups of 8 lanes keep 5 outputs each.
        float w[5];
        {
            bool hi8 = (lane & 8);
            #pragma unroll
            for (int k = 0; k < 5; k++) {
                float s = hi8 ? v[k] : v[k+5];
                float t = __shfl_xor_sync(0xffffffffu, s, 8);
                w[k] = (hi8 ? v[k+5] : v[k]) + t;
            }
        }
        // levels 3-5: complete sums within each 8-lane group
        #pragma unroll
        for (int off = 4; off; off >>= 1) {
            #pragma unroll
            for (int k = 0; k < 5; k++)
                w[k] += __shfl_xor_sync(0xffffffffu, w[k], off);
        }
        // lane group g = lane>>3 holds full sums for outputs g*5 .. g*5+4

        // ---- 4-way parallel epilogue (lanes 0,8,16,24) ----
        float epart = 0.f;
        if ((lane & 7) == 0) {
            int ob = (lane >> 3) * 5;
            float m = (zi != 0) ? 1.f : 0.f;
            const float* ce = emb + zi*AE + ob;   // cfeat = m*emb[z]
            const float* wf = d_weff + ob;
            #pragma unroll
            for (int k = 0; k < 5; k++) {
                float cf = m * __ldg(ce + k);
                float c  = (cf + fmaf(-2.0f, w[k], 256.0f)) * m;
                epart = fmaf(__ldg(wf + k), fast_tanh(c), epart);
            }
        }
        epart += __shfl_xor_sync(0xffffffffu, epart, 8);
        epart += __shfl_xor_sync(0xffffffffu, epart, 16);
        if (lane == 0) atomicAdd(out + (row >> 8), epart + d_beff);
    }
}

extern "C" void kernel_launch(void* const* d_in, const int* in_sizes, int n_in,
                              void* d_out, int out_size) {
    const int*   z    = (const int*)  d_in[0];
    const float* dist = (const float*)d_in[1];
    const float* emb  = (const float*)d_in[2];
    const float* Vw   = (const float*)d_in[3];
    const float* Vb   = (const float*)d_in[4];
    const float* W1   = (const float*)d_in[5];
    const float* b1   = (const float*)d_in[6];
    const float* W2   = (const float*)d_in[7];
    const float* b2   = (const float*)d_in[8];
    float* out = (float*)d_out;
    (void)in_sizes; (void)n_in; (void)out_size;

    cudaFuncSetAttribute(k_main, cudaFuncAttributeMaxDynamicSharedMemorySize,
                         SM_TOTAL);

    k_prep<<<TBLOCKS + ZBL + 1, 256>>>(emb, Vw, Vb, W1, b1, W2, b2, out);
    k_main<<<296, 384, SM_TOTAL>>>(dist, z, emb, out);
}

// round 15
// speedup vs baseline: 1.4321x; 1.4321x over previous
#include <cuda_runtime.h>
#include <cuda_fp16.h>
#include <math.h>

// Problem constants
#define NB 64
#define NA 256
#define NROWS (NB*NA)          // 16384 (b,i) rows
#define AE 20                  // atomemb dim
#define DF 25                  // gaussian features
#define VW_COLS 45             // AE + DF
#define NZ 256                 // z values are in [0, 256)

// Nearest-neighbor fp16 exp-table: 1537 rows over [0,5], split into three
// arrays so each gather instruction sees the max number of bank residues:
//   A: uint4 per row (outputs 0-7),  B: uint4 per row (outputs 8-15),
//   C: uint2 per row (outputs 16-19)
#define TBL 1536
#define TROWS (TBL+1)

#define CTANH 2.885390081777926814f   // 2/ln2
#define QK    0.8521437890f           // e^{-0.16}

// Device scratch (no allocations allowed)
__device__ uint4   d_tA[TROWS];
__device__ uint4   d_tB[TROWS];
__device__ uint2   d_tC[TROWS];
__device__ float4  d_ebz[NZ*5];            // exp(2*base_o) per z value (20KB)
__device__ float   d_weff[AE];
__device__ float   d_beff;

__device__ __forceinline__ float fast_tanh(float x) {
    float e;
    asm("ex2.approx.f32 %0, %1;" : "=f"(e) : "f"(x * CTANH));
    float r;
    asm("rcp.approx.f32 %0, %1;" : "=f"(r) : "f"(e + 1.0f));
    return fmaf(-2.0f, r, 1.0f);
}
__device__ __forceinline__ float rcpf(float x) {
    float r; asm("rcp.approx.f32 %0, %1;" : "=f"(r) : "f"(x)); return r;
}

// ---------- prep kernel: table + per-z eb + weff + zero out ----------
#define TBLOCKS ((TROWS*AE + 255)/256)   // table blocks (121)
#define ZBL     ((NZ*AE + 255)/256)      // per-z eb blocks (20)

__global__ void k_prep(const float* __restrict__ emb,
                       const float* __restrict__ Vw, const float* __restrict__ Vb,
                       const float* __restrict__ W1, const float* __restrict__ b1,
                       const float* __restrict__ W2, const float* __restrict__ b2,
                       float* __restrict__ out) {
    int blk = blockIdx.x;
    if (blk < TBLOCKS) {
        int idx = blk * 256 + threadIdx.x;
        if (idx >= TROWS*AE) return;
        int t = idx / AE;
        int o = idx - t*AE;
        float d = (float)t * (5.0f / (float)TBL);
        // rbf recurrence: rbf_0 = e^{-2d^2}; rbf_{k+1} = rbf_k * s_k;
        //                 s_0 = e^{0.8d - 0.08}; s_{k+1} = s_k * Q
        float rbf = __expf(-2.0f * d * d);
        float s   = __expf(0.8f * d - 0.08f);
        float g = 0.f;
        const float* vwr = Vw + o*VW_COLS + AE;
        #pragma unroll
        for (int k = 0; k < DF; k++) {
            g   = fmaf(__ldg(vwr + k), rbf, g);
            rbf = rbf * s;
            s   = s * QK;
        }
        __half h = __float2half(__expf(2.0f * g));
        if (o < 8)       ((__half*)d_tA)[t*8 + o]      = h;
        else if (o < 16) ((__half*)d_tB)[t*8 + (o-8)]  = h;
        else             ((__half*)d_tC)[t*4 + (o-16)] = h;
    } else if (blk < TBLOCKS + ZBL) {
        int idx = (blk - TBLOCKS) * 256 + threadIdx.x;
        if (idx >= NZ*AE) return;
        int zv = idx / AE;
        int o  = idx - zv*AE;
        float m = (zv != 0) ? 1.f : 0.f;
        float b = Vb[o];
        const float* er  = emb + zv*AE;
        const float* vwr = Vw + o*VW_COLS;
        #pragma unroll
        for (int f = 0; f < AE; f++)
            b = fmaf(m * __ldg(er + f), __ldg(vwr + f), b);
        ((float*)d_ebz)[idx] = __expf(2.0f * b);
    } else {
        int t = threadIdx.x;
        if (t < AE) {
            float s = 0.f;
            #pragma unroll
            for (int m = 0; m < 10; m++) s += W2[m] * W1[m*AE + t];
            d_weff[t] = s;
        }
        if (t == AE) {
            float s = b2[0];
            #pragma unroll
            for (int m = 0; m < 10; m++) s += W2[m] * b1[m];
            d_beff = s;
        }
        if (t >= 128 && t < 128 + NB) out[t - 128] = 0.f;   // zero accumulators
    }
}

// process 4 outputs from two half2 words (batch-4 reciprocal — proven optimum)
__device__ __forceinline__ void group4(unsigned w0, unsigned w1,
                                       const float* eb, float* acc) {
    float2 a = __half22float2(*(const __half2*)&w0);
    float2 b = __half22float2(*(const __half2*)&w1);
    float y0 = fmaf(a.x, eb[0], 1.0f);
    float y1 = fmaf(a.y, eb[1], 1.0f);
    float y2 = fmaf(b.x, eb[2], 1.0f);
    float y3 = fmaf(b.y, eb[3], 1.0f);
    float t01 = y0 * y1, t23 = y2 * y3;
    float r   = rcpf(t01 * t23);
    float r01 = r * t23, r23 = r * t01;
    acc[0] = fmaf(r01, y1, acc[0]);   // += 1/y0
    acc[1] = fmaf(r01, y0, acc[1]);   // += 1/y1
    acc[2] = fmaf(r23, y3, acc[2]);
    acc[3] = fmaf(r23, y2, acc[3]);
}

// smem layout (bytes)
#define SM_A 0
#define SM_B (TROWS*16)
#define SM_C (TROWS*32)
#define SM_TOTAL (TROWS*32 + TROWS*8)   // 61480 B

// ---------- main: one warp per (b,i) row; split-array gathers ----------
__global__ void __launch_bounds__(384, 2)
k_main(const float* __restrict__ dist, const int* __restrict__ z,
       const float* __restrict__ emb, float* __restrict__ out) {
    extern __shared__ char smem[];
    uint4* smA = (uint4*)(smem + SM_A);
    uint4* smB = (uint4*)(smem + SM_B);
    uint2* smC = (uint2*)(smem + SM_C);
    const int tid = threadIdx.x;
    for (int i = tid; i < TROWS; i += blockDim.x) {
        smA[i] = d_tA[i];
        smB[i] = d_tB[i];
        smC[i] = d_tC[i];
    }
    __syncthreads();

    const int lane = tid & 31;
    const int nwarps = gridDim.x * (blockDim.x >> 5);
    int gw = blockIdx.x * (blockDim.x >> 5) + (tid >> 5);

    // ---- software-pipelined row state: zi + dist quads loaded one row ahead
    int   zi = 0;
    float4 dv0 = make_float4(0.f,0.f,0.f,0.f), dv1 = dv0;
    if (gw < NROWS) {
        zi = __ldg(z + gw);
        const float4* d4 = (const float4*)(dist + (size_t)gw * NA + lane * 8);
        dv0 = __ldg(d4);
        dv1 = __ldg(d4 + 1);
    }

    for (int row = gw; row < NROWS; row += nwarps) {
        // eb: 5 uniform float4 loads from 20KB L1-resident per-z table
        float eb[AE], acc[AE];
        {
            const float4* e4 = d_ebz + zi*5;
            float4 v0 = __ldg(e4+0), v1 = __ldg(e4+1), v2 = __ldg(e4+2),
                   v3 = __ldg(e4+3), v4 = __ldg(e4+4);
            eb[0]=v0.x; eb[1]=v0.y; eb[2]=v0.z; eb[3]=v0.w;
            eb[4]=v1.x; eb[5]=v1.y; eb[6]=v1.z; eb[7]=v1.w;
            eb[8]=v2.x; eb[9]=v2.y; eb[10]=v2.z; eb[11]=v2.w;
            eb[12]=v3.x; eb[13]=v3.y; eb[14]=v3.z; eb[15]=v3.w;
            eb[16]=v4.x; eb[17]=v4.y; eb[18]=v4.z; eb[19]=v4.w;
        }
        #pragma unroll
        for (int o = 0; o < AE; o++) acc[o] = 0.f;

        float dv[8] = {dv0.x, dv0.y, dv0.z, dv0.w, dv1.x, dv1.y, dv1.z, dv1.w};
        const int zcur = zi;

        #pragma unroll
        for (int jt = 0; jt < 8; jt++) {
            int ti = __float2int_rn(dv[jt] * ((float)TBL / 5.0f));
            uint4 qa = smA[ti];
            uint4 qb = smB[ti];
            uint2 qc = smC[ti];
            group4(qa.x, qa.y, eb +  0, acc +  0);
            group4(qa.z, qa.w, eb +  4, acc +  4);
            group4(qb.x, qb.y, eb +  8, acc +  8);
            group4(qb.z, qb.w, eb + 12, acc + 12);
            group4(qc.x, qc.y, eb + 16, acc + 16);
        }

        // ---- prefetch next row's zi + dist (latency hidden by reduction) ----
        {
            int nrow = row + nwarps;
            if (nrow < NROWS) {
                zi = __ldg(z + nrow);
                const float4* d4 = (const float4*)(dist + (size_t)nrow * NA + lane * 8);
                dv0 = __ldg(d4);
                dv1 = __ldg(d4 + 1);
            }
        }

        // ---- hierarchical split reduction (R12-proven form) ----
        #pragma unroll
        for (int o = 0; o < AE; o++)
            acc[o] += __shfl_xor_sync(0xffffffffu, acc[o], 16);
        float v[10];
        {
            bool hi = (lane & 16);
            #pragma unroll
            for (int k = 0; k < 10; k++) v[k] = hi ? acc[k+10] : acc[k];
        }
        #pragma unroll
        for (int k = 0; k < 10; k++)
            v[k] += __shfl_xor_sync(0xffffffffu, v[k], 8);
        float w[5];
        {
            bool hi = (lane & 8);
            #pragma unroll
            for (int k = 0; k < 5; k++) w[k] = hi ? v[k+5] : v[k];
        }
        #pragma unroll
        for (int off = 4; off; off >>= 1) {
            #pragma unroll
            for (int k = 0; k < 5; k++)
                w[k] += __shfl_xor_sync(0xffffffffu, w[k], off);
        }
        // lane group g = lane>>3 holds full sums for outputs g*5 .. g*5+4

        // ---- 4-way parallel epilogue (lanes 0,8,16,24) ----
        float epart = 0.f;
        if ((lane & 7) == 0) {
            int ob = (lane >> 3) * 5;
            float m = (zcur != 0) ? 1.f : 0.f;
            const float* ce = emb + zcur*AE + ob;   // cfeat = m*emb[z]
            const float* wf = d_weff + ob;
            #pragma unroll
            for (int k = 0; k < 5; k++) {
                float cf = m * __ldg(ce + k);
                float c  = (cf + fmaf(-2.0f, w[k], 256.0f)) * m;
                epart = fmaf(__ldg(wf + k), fast_tanh(c), epart);
            }
        }
        epart += __shfl_xor_sync(0xffffffffu, epart, 8);
        epart += __shfl_xor_sync(0xffffffffu, epart, 16);
        if (lane == 0) atomicAdd(out + (row >> 8), epart + d_beff);
    }
}

extern "C" void kernel_launch(void* const* d_in, const int* in_sizes, int n_in,
                              void* d_out, int out_size) {
    const int*   z    = (const int*)  d_in[0];
    const float* dist = (const float*)d_in[1];
    const float* emb  = (const float*)d_in[2];
    const float* Vw   = (const float*)d_in[3];
    const float* Vb   = (const float*)d_in[4];
    const float* W1   = (const float*)d_in[5];
    const float* b1   = (const float*)d_in[6];
    const float* W2   = (const float*)d_in[7];
    const float* b2   = (const float*)d_in[8];
    float* out = (float*)d_out;
    (void)in_sizes; (void)n_in; (void)out_size;

    cudaFuncSetAttribute(k_main, cudaFuncAttributeMaxDynamicSharedMemorySize,
                         SM_TOTAL);

    k_prep<<<TBLOCKS + ZBL + 1, 256>>>(emb, Vw, Vb, W1, b1, W2, b2, out);
    k_main<<<296, 384, SM_TOTAL>>>(dist, z, emb, out);
}

// round 17
// speedup vs baseline: 1.5262x; 1.0656x over previous
#include <cuda_runtime.h>
#include <cuda_fp16.h>
#include <math.h>

// Problem constants
#define NB 64
#define NA 256
#define NROWS (NB*NA)          // 16384 (b,i) rows
#define AE 20                  // atomemb dim
#define DF 25                  // gaussian features
#define VW_COLS 45             // AE + DF
#define NZ 256                 // z values are in [0, 256)

// Nearest-neighbor fp16 exp-table: 1537 rows over [0,5], split into three
// arrays so each gather instruction sees the max number of bank residues:
//   A: uint4 per row (outputs 0-7),  B: uint4 per row (outputs 8-15),
//   C: uint2 per row (outputs 16-19)
#define TBL 1536
#define TROWS (TBL+1)

#define CTANH 2.885390081777926814f   // 2/ln2
#define QK    0.8521437890f           // e^{-0.16}

// Device scratch (no allocations allowed)
__device__ uint4   d_tA[TROWS];
__device__ uint4   d_tB[TROWS];
__device__ uint2   d_tC[TROWS];
__device__ float4  d_ebz[NZ*5];            // exp(2*base_o) per z value (20KB)
__device__ float   d_weff[AE];
__device__ float   d_beff;

__device__ __forceinline__ float fast_tanh(float x) {
    float e;
    asm("ex2.approx.f32 %0, %1;" : "=f"(e) : "f"(x * CTANH));
    float r;
    asm("rcp.approx.f32 %0, %1;" : "=f"(r) : "f"(e + 1.0f));
    return fmaf(-2.0f, r, 1.0f);
}
__device__ __forceinline__ float rcpf(float x) {
    float r; asm("rcp.approx.f32 %0, %1;" : "=f"(r) : "f"(x)); return r;
}

// ---------- prep kernel: table + per-z eb + weff + zero out ----------
#define TBLOCKS ((TROWS*AE + 255)/256)   // table blocks (121)
#define ZBL     ((NZ*AE + 255)/256)      // per-z eb blocks (20)

__global__ void k_prep(const float* __restrict__ emb,
                       const float* __restrict__ Vw, const float* __restrict__ Vb,
                       const float* __restrict__ W1, const float* __restrict__ b1,
                       const float* __restrict__ W2, const float* __restrict__ b2,
                       float* __restrict__ out) {
    int blk = blockIdx.x;
    if (blk < TBLOCKS) {
        int idx = blk * 256 + threadIdx.x;
        if (idx >= TROWS*AE) return;
        int t = idx / AE;
        int o = idx - t*AE;
        float d = (float)t * (5.0f / (float)TBL);
        // rbf recurrence: rbf_0 = e^{-2d^2}; rbf_{k+1} = rbf_k * s_k;
        //                 s_0 = e^{0.8d - 0.08}; s_{k+1} = s_k * Q
        float rbf = __expf(-2.0f * d * d);
        float s   = __expf(0.8f * d - 0.08f);
        float g = 0.f;
        const float* vwr = Vw + o*VW_COLS + AE;
        #pragma unroll
        for (int k = 0; k < DF; k++) {
            g   = fmaf(__ldg(vwr + k), rbf, g);
            rbf = rbf * s;
            s   = s * QK;
        }
        __half h = __float2half(__expf(2.0f * g));
        if (o < 8)       ((__half*)d_tA)[t*8 + o]      = h;
        else if (o < 16) ((__half*)d_tB)[t*8 + (o-8)]  = h;
        else             ((__half*)d_tC)[t*4 + (o-16)] = h;
    } else if (blk < TBLOCKS + ZBL) {
        int idx = (blk - TBLOCKS) * 256 + threadIdx.x;
        if (idx >= NZ*AE) return;
        int zv = idx / AE;
        int o  = idx - zv*AE;
        float m = (zv != 0) ? 1.f : 0.f;
        float b = Vb[o];
        const float* er  = emb + zv*AE;
        const float* vwr = Vw + o*VW_COLS;
        #pragma unroll
        for (int f = 0; f < AE; f++)
            b = fmaf(m * __ldg(er + f), __ldg(vwr + f), b);
        ((float*)d_ebz)[idx] = __expf(2.0f * b);
    } else {
        int t = threadIdx.x;
        if (t < AE) {
            float s = 0.f;
            #pragma unroll
            for (int m = 0; m < 10; m++) s += W2[m] * W1[m*AE + t];
            d_weff[t] = s;
        }
        if (t == AE) {
            float s = b2[0];
            #pragma unroll
            for (int m = 0; m < 10; m++) s += W2[m] * b1[m];
            d_beff = s;
        }
        if (t >= 128 && t < 128 + NB) out[t - 128] = 0.f;   // zero accumulators
    }
}

// process 4 outputs from two half2 words (batch-4 reciprocal — proven optimum)
__device__ __forceinline__ void group4(unsigned w0, unsigned w1,
                                       const float* eb, float* acc) {
    float2 a = __half22float2(*(const __half2*)&w0);
    float2 b = __half22float2(*(const __half2*)&w1);
    float y0 = fmaf(a.x, eb[0], 1.0f);
    float y1 = fmaf(a.y, eb[1], 1.0f);
    float y2 = fmaf(b.x, eb[2], 1.0f);
    float y3 = fmaf(b.y, eb[3], 1.0f);
    float t01 = y0 * y1, t23 = y2 * y3;
    float r   = rcpf(t01 * t23);
    float r01 = r * t23, r23 = r * t01;
    acc[0] = fmaf(r01, y1, acc[0]);   // += 1/y0
    acc[1] = fmaf(r01, y0, acc[1]);   // += 1/y1
    acc[2] = fmaf(r23, y3, acc[2]);
    acc[3] = fmaf(r23, y2, acc[3]);
}

// smem layout (bytes) — SM_E rounded up to 16B alignment (TROWS*40 = 61480
// is only 8B-aligned; float4 loads from smE require 16B).
#define SM_A 0
#define SM_B (TROWS*16)
#define SM_C (TROWS*32)
#define SM_E (((TROWS*32 + TROWS*8) + 15) & ~15)      // 61488
#define SM_TOTAL (SM_E + NZ*5*16)                     // 61488 + 20480 = 81968 B

// ---------- main: one warp per (b,i) row; split-array gathers ----------
__global__ void __launch_bounds__(384, 2)
k_main(const float* __restrict__ dist, const int* __restrict__ z,
       const float* __restrict__ emb, float* __restrict__ out) {
    extern __shared__ char smem[];
    uint4*  smA = (uint4*)(smem + SM_A);
    uint4*  smB = (uint4*)(smem + SM_B);
    uint2*  smC = (uint2*)(smem + SM_C);
    float4* smE = (float4*)(smem + SM_E);
    const int tid = threadIdx.x;
    for (int i = tid; i < TROWS; i += blockDim.x) {
        smA[i] = d_tA[i];
        smB[i] = d_tB[i];
        smC[i] = d_tC[i];
    }
    for (int i = tid; i < NZ*5; i += blockDim.x) smE[i] = d_ebz[i];
    __syncthreads();

    const int lane = tid & 31;
    const int nwarps = gridDim.x * (blockDim.x >> 5);
    int gw = blockIdx.x * (blockDim.x >> 5) + (tid >> 5);

    // ---- software-pipelined row state: zi + dist quads loaded one row ahead
    int   zi = 0;
    float4 dv0 = make_float4(0.f,0.f,0.f,0.f), dv1 = dv0;
    if (gw < NROWS) {
        zi = __ldg(z + gw);
        const float4* d4 = (const float4*)(dist + (size_t)gw * NA + lane * 8);
        dv0 = __ldg(d4);
        dv1 = __ldg(d4 + 1);
    }

    for (int row = gw; row < NROWS; row += nwarps) {
        // eb: 5 broadcast LDS.128 from the block-resident ebz copy
        float eb[AE], acc[AE];
        {
            const float4* e4 = smE + zi*5;
            float4 v0 = e4[0], v1 = e4[1], v2 = e4[2], v3 = e4[3], v4 = e4[4];
            eb[0]=v0.x; eb[1]=v0.y; eb[2]=v0.z; eb[3]=v0.w;
            eb[4]=v1.x; eb[5]=v1.y; eb[6]=v1.z; eb[7]=v1.w;
            eb[8]=v2.x; eb[9]=v2.y; eb[10]=v2.z; eb[11]=v2.w;
            eb[12]=v3.x; eb[13]=v3.y; eb[14]=v3.z; eb[15]=v3.w;
            eb[16]=v4.x; eb[17]=v4.y; eb[18]=v4.z; eb[19]=v4.w;
        }
        #pragma unroll
        for (int o = 0; o < AE; o++) acc[o] = 0.f;

        float dv[8] = {dv0.x, dv0.y, dv0.z, dv0.w, dv1.x, dv1.y, dv1.z, dv1.w};
        const int zcur = zi;

        #pragma unroll
        for (int jt = 0; jt < 8; jt++) {
            int ti = __float2int_rn(dv[jt] * ((float)TBL / 5.0f));
            uint4 qa = smA[ti];
            uint4 qb = smB[ti];
            uint2 qc = smC[ti];
            group4(qa.x, qa.y, eb +  0, acc +  0);
            group4(qa.z, qa.w, eb +  4, acc +  4);
            group4(qb.x, qb.y, eb +  8, acc +  8);
            group4(qb.z, qb.w, eb + 12, acc + 12);
            group4(qc.x, qc.y, eb + 16, acc + 16);
        }

        // ---- prefetch next row's zi + dist (latency hidden by reduction) ----
        {
            int nrow = row + nwarps;
            if (nrow < NROWS) {
                zi = __ldg(z + nrow);
                const float4* d4 = (const float4*)(dist + (size_t)nrow * NA + lane * 8);
                dv0 = __ldg(d4);
                dv1 = __ldg(d4 + 1);
            }
        }

        // ---- hierarchical split reduction (R12-proven form) ----
        #pragma unroll
        for (int o = 0; o < AE; o++)
            acc[o] += __shfl_xor_sync(0xffffffffu, acc[o], 16);
        float v[10];
        {
            bool hi = (lane & 16);
            #pragma unroll
            for (int k = 0; k < 10; k++) v[k] = hi ? acc[k+10] : acc[k];
        }
        #pragma unroll
        for (int k = 0; k < 10; k++)
            v[k] += __shfl_xor_sync(0xffffffffu, v[k], 8);
        float w[5];
        {
            bool hi = (lane & 8);
            #pragma unroll
            for (int k = 0; k < 5; k++) w[k] = hi ? v[k+5] : v[k];
        }
        #pragma unroll
        for (int off = 4; off; off >>= 1) {
            #pragma unroll
            for (int k = 0; k < 5; k++)
                w[k] += __shfl_xor_sync(0xffffffffu, w[k], off);
        }
        // lane group g = lane>>3 holds full sums for outputs g*5 .. g*5+4

        // ---- 4-way parallel epilogue (lanes 0,8,16,24) ----
        float epart = 0.f;
        if ((lane & 7) == 0) {
            int ob = (lane >> 3) * 5;
            float m = (zcur != 0) ? 1.f : 0.f;
            const float* ce = emb + zcur*AE + ob;   // cfeat = m*emb[z]
            const float* wf = d_weff + ob;
            #pragma unroll
            for (int k = 0; k < 5; k++) {
                float cf = m * __ldg(ce + k);
                float c  = (cf + fmaf(-2.0f, w[k], 256.0f)) * m;
                epart = fmaf(__ldg(wf + k), fast_tanh(c), epart);
            }
        }
        epart += __shfl_xor_sync(0xffffffffu, epart, 8);
        epart += __shfl_xor_sync(0xffffffffu, epart, 16);
        if (lane == 0) atomicAdd(out + (row >> 8), epart + d_beff);
    }
}

extern "C" void kernel_launch(void* const* d_in, const int* in_sizes, int n_in,
                              void* d_out, int out_size) {
    const int*   z    = (const int*)  d_in[0];
    const float* dist = (const float*)d_in[1];
    const float* emb  = (const float*)d_in[2];
    const float* Vw   = (const float*)d_in[3];
    const float* Vb   = (const float*)d_in[4];
    const float* W1   = (const float*)d_in[5];
    const float* b1   = (const float*)d_in[6];
    const float* W2   = (const float*)d_in[7];
    const float* b2   = (const float*)d_in[8];
    float* out = (float*)d_out;
    (void)in_sizes; (void)n_in; (void)out_size;

    cudaFuncSetAttribute(k_main, cudaFuncAttributeMaxDynamicSharedMemorySize,
                         SM_TOTAL);

    k_prep<<<TBLOCKS + ZBL + 1, 256>>>(emb, Vw, Vb, W1, b1, W2, b2, out);
    k_main<<<296, 384, SM_TOTAL>>>(dist, z, emb, out);
}